// round 3
// baseline (speedup 1.0000x reference)
#include <cuda_runtime.h>
#include <cuda_bf16.h>
#include <math.h>

#define TIMESTEPS 1000
#define BB 4
#define NN 2048
#define EE (NN * (NN - 1) / 2)   // 2096128
#define NBLK_X 1024              // row pairs per batch
#define NBLK (NBLK_X * BB)       // 4096 total blocks
#define NTHREADS 256

__device__ double g_part[NBLK];
__device__ unsigned int g_count = 0;

__device__ __forceinline__ float row_sum(
    const int* __restrict__ arow,
    const float* __restrict__ urow,
    const float* __restrict__ qrow,
    int L,
    float flip_e, float one_m_fe,
    float flip_p, float one_m_fp,
    float flip0, float one_m_f0)
{
    float s = 0.0f;
    const int nv4 = L >> 2;

    // vectorized main body: adj/u rows are 16B-aligned (row stride = 8192B)
    const int4*   a4 = (const int4*)arow;
    const float4* u4 = (const float4*)urow;
    for (int v = threadIdx.x; v < nv4; v += NTHREADS) {
        const int4   a = a4[v];
        const float4 uu = u4[v];
        const int jb = v << 2;
        const float q0 = __ldg(qrow + jb + 0);
        const float q1 = __ldg(qrow + jb + 1);
        const float q2 = __ldg(qrow + jb + 2);
        const float q3 = __ldg(qrow + jb + 3);

        #pragma unroll
        for (int k = 0; k < 4; k++) {
            const int   a_k = (k == 0) ? a.x : (k == 1) ? a.y : (k == 2) ? a.z : a.w;
            const float u_k = (k == 0) ? uu.x : (k == 1) ? uu.y : (k == 2) ? uu.z : uu.w;
            const float q_k = (k == 0) ? q0 : (k == 1) ? q1 : (k == 2) ? q2 : q3;

            const float p1 = a_k ? one_m_fe : flip_e;
            const int   x  = (u_k < p1) ? 1 : 0;
            const float L1 = x ? one_m_f0 : flip0;
            const float P1 = a_k ? one_m_fp : flip_p;
            const float Ev = (a_k == x) ? one_m_fe : flip_e;
            const float qt = L1 * P1 / Ev;
            s += fmaxf(q_k, 0.0f) - q_k * qt + log1pf(expf(-fabsf(q_k)));
        }
    }

    // scalar tail
    for (int j = (nv4 << 2) + threadIdx.x; j < L; j += NTHREADS) {
        const int   a_k = arow[j];
        const float u_k = urow[j];
        const float q_k = __ldg(qrow + j);
        const float p1 = a_k ? one_m_fe : flip_e;
        const int   x  = (u_k < p1) ? 1 : 0;
        const float L1 = x ? one_m_f0 : flip0;
        const float P1 = a_k ? one_m_fp : flip_p;
        const float Ev = (a_k == x) ? one_m_fe : flip_e;
        const float qt = L1 * P1 / Ev;
        s += fmaxf(q_k, 0.0f) - q_k * qt + log1pf(expf(-fabsf(q_k)));
    }
    return s;
}

__global__ __launch_bounds__(NTHREADS) void diffusion_loss_kernel(
    const int* __restrict__ adj,
    const int* __restrict__ t,
    const float* __restrict__ u,
    const float* __restrict__ q,
    float* __restrict__ out)
{
    const int bk = blockIdx.x;          // 0..1023
    const int b  = blockIdx.y;          // batch
    const int r1 = bk + 1;
    const int r2 = 2047 - bk;           // pair partner; r1==r2 only at bk=1023

    const int tb = t[b];
    const float flip_e = 0.5f * (1.0f - powf(0.98f, (float)(tb + 1)));
    const int   tp     = (tb == 0) ? (TIMESTEPS - 1) : (tb - 1);   // JAX wraps Qt[-1] -> Qt[999]
    const float flip_p = 0.5f * (1.0f - powf(0.98f, (float)(tp + 1)));
    const float flip0  = 0.5f * (1.0f - 0.98f);
    const float one_m_fe = 1.0f - flip_e;
    const float one_m_fp = 1.0f - flip_p;
    const float one_m_f0 = 1.0f - flip0;

    const size_t base = (size_t)b * NN * NN;
    const float* qb   = q + (size_t)b * EE;

    float s = row_sum(adj + base + (size_t)r1 * NN,
                      u   + base + (size_t)r1 * NN,
                      qb + ((size_t)r1 * (r1 - 1)) / 2, r1,
                      flip_e, one_m_fe, flip_p, one_m_fp, flip0, one_m_f0);
    if (r2 > r1) {
        s += row_sum(adj + base + (size_t)r2 * NN,
                     u   + base + (size_t)r2 * NN,
                     qb + ((size_t)r2 * (r2 - 1)) / 2, r2,
                     flip_e, one_m_fe, flip_p, one_m_fp, flip0, one_m_f0);
    }

    // block reduce
    for (int off = 16; off > 0; off >>= 1)
        s += __shfl_down_sync(0xFFFFFFFFu, s, off);
    __shared__ float warp_sums[NTHREADS / 32];
    const int lane = threadIdx.x & 31;
    const int wid  = threadIdx.x >> 5;
    if (lane == 0) warp_sums[wid] = s;
    __syncthreads();
    const int blk_id = blockIdx.y * NBLK_X + blockIdx.x;
    if (wid == 0) {
        float v = (lane < (NTHREADS >> 5)) ? warp_sums[lane] : 0.0f;
        for (int off = 4; off > 0; off >>= 1)
            v += __shfl_down_sync(0xFFFFFFFFu, v, off);
        if (lane == 0) g_part[blk_id] = (double)v;
    }

    // last-block final reduction (deterministic: counter reset each call)
    __shared__ bool is_last;
    __threadfence();
    __syncthreads();
    if (threadIdx.x == 0) {
        unsigned int c = atomicAdd(&g_count, 1u);
        is_last = (c == (unsigned int)(NBLK - 1));
    }
    __syncthreads();
    if (is_last) {
        double ds = 0.0;
        for (int i = threadIdx.x; i < NBLK; i += NTHREADS)
            ds += g_part[i];
        for (int off = 16; off > 0; off >>= 1)
            ds += __shfl_down_sync(0xFFFFFFFFu, ds, off);
        __shared__ double dwarp[NTHREADS / 32];
        if (lane == 0) dwarp[wid] = ds;
        __syncthreads();
        if (wid == 0) {
            double dv = (lane < (NTHREADS >> 5)) ? dwarp[lane] : 0.0;
            for (int off = 4; off > 0; off >>= 1)
                dv += __shfl_down_sync(0xFFFFFFFFu, dv, off);
            if (lane == 0) {
                out[0] = (float)(dv / (double)((size_t)BB * EE));
                g_count = 0;   // reset for next graph replay
            }
        }
    }
}

extern "C" void kernel_launch(void* const* d_in, const int* in_sizes, int n_in,
                              void* d_out, int out_size)
{
    const int*   adj = (const int*)d_in[0];    // (B,N,N) int32
    const int*   t   = (const int*)d_in[1];    // (B,)    int32
    const float* u   = (const float*)d_in[2];  // (B,N,N) float32
    const float* q   = (const float*)d_in[3];  // (B,E)   float32
    float* out = (float*)d_out;

    dim3 grid(NBLK_X, BB);
    diffusion_loss_kernel<<<grid, NTHREADS>>>(adj, t, u, q, out);
}

// round 4
// speedup vs baseline: 1.1739x; 1.1739x over previous
#include <cuda_runtime.h>
#include <cuda_bf16.h>
#include <math.h>

#define TIMESTEPS 1000
#define BB 4
#define NN 2048
#define EE (NN * (NN - 1) / 2)   // 2096128
#define NBLK_X 1024              // row pairs per batch
#define NBLK (NBLK_X * BB)       // 4096 total blocks
#define NTHREADS 256

__device__ double g_part[NBLK];
__device__ unsigned int g_count = 0;

// softplus(-|x|) = log(1 + exp(-|x|)) via fast MUFU path; plenty of precision
// headroom vs 1e-3 rel-err threshold.
__device__ __forceinline__ float softplus_neg_abs(float q)
{
    const float z = __expf(-fabsf(q));       // FMUL + MUFU.EX2
    return __logf(1.0f + z);                 // FADD + MUFU.LG2 + FMUL
}

// per-element loss given precomputed tables
__device__ __forceinline__ float elem_loss(
    int a, float uu, float qa,
    float flip_e, float one_m_fe,
    float qt00, float qt01, float qt10, float qt11)
{
    const float p1 = a ? one_m_fe : flip_e;      // P(x=1 | adj)
    const bool  x  = (uu < p1);
    const float qt = a ? (x ? qt11 : qt10)
                       : (x ? qt01 : qt00);      // 3 SELs, no div
    // max(q,0) - q*qt + softplus(-|q|)
    return fmaf(-qa, qt, fmaxf(qa, 0.0f)) + softplus_neg_abs(qa);
}

__device__ __forceinline__ float row_sum(
    const int* __restrict__ arow,
    const float* __restrict__ urow,
    const float* __restrict__ qrow,
    int L,
    float flip_e, float one_m_fe,
    float qt00, float qt01, float qt10, float qt11)
{
    float s = 0.0f;
    const int nv4 = L >> 2;

    const int4*   a4 = (const int4*)arow;   // rows are 8192B-strided -> 16B aligned
    const float4* u4 = (const float4*)urow;
    for (int v = threadIdx.x; v < nv4; v += NTHREADS) {
        const int4   a = a4[v];
        const float4 uu = u4[v];
        const int jb = v << 2;
        const float q0 = __ldg(qrow + jb + 0);
        const float q1 = __ldg(qrow + jb + 1);
        const float q2 = __ldg(qrow + jb + 2);
        const float q3 = __ldg(qrow + jb + 3);

        s += elem_loss(a.x, uu.x, q0, flip_e, one_m_fe, qt00, qt01, qt10, qt11);
        s += elem_loss(a.y, uu.y, q1, flip_e, one_m_fe, qt00, qt01, qt10, qt11);
        s += elem_loss(a.z, uu.z, q2, flip_e, one_m_fe, qt00, qt01, qt10, qt11);
        s += elem_loss(a.w, uu.w, q3, flip_e, one_m_fe, qt00, qt01, qt10, qt11);
    }

    for (int j = (nv4 << 2) + threadIdx.x; j < L; j += NTHREADS)
        s += elem_loss(arow[j], urow[j], __ldg(qrow + j),
                       flip_e, one_m_fe, qt00, qt01, qt10, qt11);
    return s;
}

__global__ __launch_bounds__(NTHREADS) void diffusion_loss_kernel(
    const int* __restrict__ adj,
    const int* __restrict__ t,
    const float* __restrict__ u,
    const float* __restrict__ q,
    float* __restrict__ out)
{
    const int bk = blockIdx.x;          // 0..1023
    const int b  = blockIdx.y;          // batch
    const int r1 = bk + 1;
    const int r2 = 2047 - bk;

    const int tb = t[b];
    const float flip_e = 0.5f * (1.0f - powf(0.98f, (float)(tb + 1)));
    const int   tp     = (tb == 0) ? (TIMESTEPS - 1) : (tb - 1);   // JAX wraps Qt[-1] -> Qt[999]
    const float flip_p = 0.5f * (1.0f - powf(0.98f, (float)(tp + 1)));
    const float flip0  = 0.01f;               // 0.5*(1-0.98)
    const float one_m_fe = 1.0f - flip_e;
    const float one_m_fp = 1.0f - flip_p;
    const float one_m_f0 = 1.0f - flip0;

    // qt(a,x) = Qt[0][x,1] * Qt[t-1][a,1] / Qt[t][a,x]  -- only 4 values
    const float qt00 = flip0    * flip_p    / one_m_fe;   // a=0,x=0
    const float qt01 = one_m_f0 * flip_p    / flip_e;     // a=0,x=1
    const float qt10 = flip0    * one_m_fp  / flip_e;     // a=1,x=0
    const float qt11 = one_m_f0 * one_m_fp  / one_m_fe;   // a=1,x=1

    const size_t base = (size_t)b * NN * NN;
    const float* qb   = q + (size_t)b * EE;

    float s = row_sum(adj + base + (size_t)r1 * NN,
                      u   + base + (size_t)r1 * NN,
                      qb + ((size_t)r1 * (r1 - 1)) / 2, r1,
                      flip_e, one_m_fe, qt00, qt01, qt10, qt11);
    if (r2 > r1) {
        s += row_sum(adj + base + (size_t)r2 * NN,
                     u   + base + (size_t)r2 * NN,
                     qb + ((size_t)r2 * (r2 - 1)) / 2, r2,
                     flip_e, one_m_fe, qt00, qt01, qt10, qt11);
    }

    // block reduce
    for (int off = 16; off > 0; off >>= 1)
        s += __shfl_down_sync(0xFFFFFFFFu, s, off);
    __shared__ float warp_sums[NTHREADS / 32];
    const int lane = threadIdx.x & 31;
    const int wid  = threadIdx.x >> 5;
    if (lane == 0) warp_sums[wid] = s;
    __syncthreads();
    const int blk_id = blockIdx.y * NBLK_X + blockIdx.x;
    if (wid == 0) {
        float v = (lane < (NTHREADS >> 5)) ? warp_sums[lane] : 0.0f;
        for (int off = 4; off > 0; off >>= 1)
            v += __shfl_down_sync(0xFFFFFFFFu, v, off);
        if (lane == 0) g_part[blk_id] = (double)v;
    }

    // last-block final reduction (counter reset each call -> graph-replay safe)
    __shared__ bool is_last;
    __threadfence();
    __syncthreads();
    if (threadIdx.x == 0) {
        unsigned int c = atomicAdd(&g_count, 1u);
        is_last = (c == (unsigned int)(NBLK - 1));
    }
    __syncthreads();
    if (is_last) {
        double ds = 0.0;
        for (int i = threadIdx.x; i < NBLK; i += NTHREADS)
            ds += g_part[i];
        for (int off = 16; off > 0; off >>= 1)
            ds += __shfl_down_sync(0xFFFFFFFFu, ds, off);
        __shared__ double dwarp[NTHREADS / 32];
        if (lane == 0) dwarp[wid] = ds;
        __syncthreads();
        if (wid == 0) {
            double dv = (lane < (NTHREADS >> 5)) ? dwarp[lane] : 0.0;
            for (int off = 4; off > 0; off >>= 1)
                dv += __shfl_down_sync(0xFFFFFFFFu, dv, off);
            if (lane == 0) {
                out[0] = (float)(dv / (double)((size_t)BB * EE));
                g_count = 0;
            }
        }
    }
}

extern "C" void kernel_launch(void* const* d_in, const int* in_sizes, int n_in,
                              void* d_out, int out_size)
{
    const int*   adj = (const int*)d_in[0];    // (B,N,N) int32
    const int*   t   = (const int*)d_in[1];    // (B,)    int32
    const float* u   = (const float*)d_in[2];  // (B,N,N) float32
    const float* q   = (const float*)d_in[3];  // (B,E)   float32
    float* out = (float*)d_out;

    dim3 grid(NBLK_X, BB);
    diffusion_loss_kernel<<<grid, NTHREADS>>>(adj, t, u, q, out);
}

// round 5
// speedup vs baseline: 1.4211x; 1.2105x over previous
#include <cuda_runtime.h>
#include <cuda_bf16.h>
#include <math.h>

#define TIMESTEPS 1000
#define BB 4
#define NN 2048
#define EE (NN * (NN - 1) / 2)   // 2096128
#define NBLK_X 1024              // row pairs per batch
#define NBLK (NBLK_X * BB)       // 4096 total blocks
#define NTHREADS 256

__device__ double g_part[NBLK];
__device__ unsigned int g_count = 0;

__device__ __forceinline__ float elem_loss(
    int a, float uu, float qa,
    float flip_e, float one_m_fe,
    float qt00, float qt01, float qt10, float qt11)
{
    const float p1 = a ? one_m_fe : flip_e;
    const bool  x  = (uu < p1);
    const float qt = a ? (x ? qt11 : qt10)
                       : (x ? qt01 : qt00);
    const float z  = __expf(-fabsf(qa));
    const float sp = __logf(1.0f + z);
    return fmaf(-qa, qt, fmaxf(qa, 0.0f)) + sp;
}

__global__ __launch_bounds__(NTHREADS) void diffusion_loss_kernel(
    const int* __restrict__ adj,
    const int* __restrict__ t,
    const float* __restrict__ u,
    const float* __restrict__ q,
    float* __restrict__ out)
{
    const int bk = blockIdx.x;          // 0..1023
    const int b  = blockIdx.y;          // batch
    const int r1 = bk + 1;
    const int r2 = 2047 - bk;
    const int Ltot = (r1 == r2) ? r1 : (r1 + r2);   // 2048, except 1024 at bk=1023

    const int tb = t[b];
    const float flip_e = 0.5f * (1.0f - powf(0.98f, (float)(tb + 1)));
    const int   tp     = (tb == 0) ? (TIMESTEPS - 1) : (tb - 1);   // JAX wrap Qt[-1]->Qt[999]
    const float flip_p = 0.5f * (1.0f - powf(0.98f, (float)(tp + 1)));
    const float flip0  = 0.01f;
    const float one_m_fe = 1.0f - flip_e;
    const float one_m_fp = 1.0f - flip_p;
    const float one_m_f0 = 1.0f - flip0;

    // 4-entry q_target table (kills per-element division)
    const float qt00 = flip0    * flip_p    / one_m_fe;
    const float qt01 = one_m_f0 * flip_p    / flip_e;
    const float qt10 = flip0    * one_m_fp  / flip_e;
    const float qt11 = one_m_f0 * one_m_fp  / one_m_fe;

    // 32-bit offsets (all indices < 2^25 per batch; max abs index ~16.8M)
    const int*   A = adj + b * (NN * NN);
    const float* U = u   + b * (NN * NN);
    const float* Q = q   + b * EE;
    const int o1 = r1 * NN;                 // adj/u offset for virtual v < r1
    const int o2 = r2 * NN - r1;            // adj/u offset for v >= r1
    const int p1off = (r1 * (r1 - 1)) / 2;  // q offset for v < r1
    const int p2off = (r2 * (r2 - 1)) / 2 - r1;

    float s = 0.0f;
    int v = threadIdx.x;

    // main unrolled loop: 12 front-batched independent scalar LDGs
    for (; v + 3 * NTHREADS < Ltot; v += 4 * NTHREADS) {
        int   ai[4], qi[4];
        int   a[4];
        float uu[4], qa[4];
        #pragma unroll
        for (int k = 0; k < 4; k++) {
            const int  vk = v + k * NTHREADS;
            const bool lo = vk < r1;
            ai[k] = vk + (lo ? o1 : o2);
            qi[k] = vk + (lo ? p1off : p2off);
        }
        #pragma unroll
        for (int k = 0; k < 4; k++) a[k]  = A[ai[k]];
        #pragma unroll
        for (int k = 0; k < 4; k++) uu[k] = U[ai[k]];
        #pragma unroll
        for (int k = 0; k < 4; k++) qa[k] = Q[qi[k]];
        #pragma unroll
        for (int k = 0; k < 4; k++)
            s += elem_loss(a[k], uu[k], qa[k], flip_e, one_m_fe,
                           qt00, qt01, qt10, qt11);
    }
    // tail (only the bk=1023 block with Ltot=1024, plus nothing else: 2048 % 1024 == 0)
    for (; v < Ltot; v += NTHREADS) {
        const bool lo = v < r1;
        const int  ai = v + (lo ? o1 : o2);
        const int  qi = v + (lo ? p1off : p2off);
        s += elem_loss(A[ai], U[ai], Q[qi], flip_e, one_m_fe,
                       qt00, qt01, qt10, qt11);
    }

    // block reduce
    for (int off = 16; off > 0; off >>= 1)
        s += __shfl_down_sync(0xFFFFFFFFu, s, off);
    __shared__ float warp_sums[NTHREADS / 32];
    const int lane = threadIdx.x & 31;
    const int wid  = threadIdx.x >> 5;
    if (lane == 0) warp_sums[wid] = s;
    __syncthreads();
    const int blk_id = blockIdx.y * NBLK_X + blockIdx.x;
    if (wid == 0) {
        float w = (lane < (NTHREADS >> 5)) ? warp_sums[lane] : 0.0f;
        for (int off = 4; off > 0; off >>= 1)
            w += __shfl_down_sync(0xFFFFFFFFu, w, off);
        if (lane == 0) g_part[blk_id] = (double)w;
    }

    // last-block final reduction (counter reset -> graph-replay safe)
    __shared__ bool is_last;
    __threadfence();
    __syncthreads();
    if (threadIdx.x == 0) {
        unsigned int c = atomicAdd(&g_count, 1u);
        is_last = (c == (unsigned int)(NBLK - 1));
    }
    __syncthreads();
    if (is_last) {
        double ds = 0.0;
        for (int i = threadIdx.x; i < NBLK; i += NTHREADS)
            ds += g_part[i];
        for (int off = 16; off > 0; off >>= 1)
            ds += __shfl_down_sync(0xFFFFFFFFu, ds, off);
        __shared__ double dwarp[NTHREADS / 32];
        if (lane == 0) dwarp[wid] = ds;
        __syncthreads();
        if (wid == 0) {
            double dv = (lane < (NTHREADS >> 5)) ? dwarp[lane] : 0.0;
            for (int off = 4; off > 0; off >>= 1)
                dv += __shfl_down_sync(0xFFFFFFFFu, dv, off);
            if (lane == 0) {
                out[0] = (float)(dv / (double)((size_t)BB * EE));
                g_count = 0;
            }
        }
    }
}

extern "C" void kernel_launch(void* const* d_in, const int* in_sizes, int n_in,
                              void* d_out, int out_size)
{
    const int*   adj = (const int*)d_in[0];    // (B,N,N) int32
    const int*   t   = (const int*)d_in[1];    // (B,)    int32
    const float* u   = (const float*)d_in[2];  // (B,N,N) float32
    const float* q   = (const float*)d_in[3];  // (B,E)   float32
    float* out = (float*)d_out;

    dim3 grid(NBLK_X, BB);
    diffusion_loss_kernel<<<grid, NTHREADS>>>(adj, t, u, q, out);
}